// round 15
// baseline (speedup 1.0000x reference)
#include <cuda_runtime.h>
#include <cuda_fp16.h>
#include <math.h>
#include <stdint.h>

// ---------------- problem constants ----------------
#define N_MAX   50000
#define E_MAX   800000
#define IN_CH   128
#define HIDC    32
#define H1CH    128
#define CATCH   160
#define OUTCH   64
#define NEG_SLOPE 0.2f
#define BN_EPS    1e-5f

// ---------------- device scratch ----------------
__device__ __half g_xl1h[N_MAX * 128];  // conv1 xl, fp16 (gathered per-edge)
__device__ float  g_xr1 [N_MAX * 128];  // conv1 xr, fp32
__device__ float  g_h1  [N_MAX * H1CH];
__device__ __half g_xl2h[N_MAX * 32];   // conv2 xl, fp16 (gathered per-edge)
__device__ float  g_xr2 [N_MAX * 32];   // conv2 xr, fp32
__device__ float  g_h2e [N_MAX * HIDC];

__device__ __half g_w1h[256 * 128];     // [n][k] fp16: n<128 -> W1l^T, else W1r^T
__device__ __half g_w2h[64 * 128];      // [n][k] fp16: n<32 -> W2l^T, else W2r^T
__device__ __half g_wch[64 * 160];      // [n][k] fp16: Wc^T

__device__ int   g_counts[N_MAX];       // zero at load; self-zeroing via atomicSub in k_fill
__device__ int   g_rowptr[N_MAX + 1];
__device__ int   g_srcs  [E_MAX];

__device__ float g_sum  [H1CH];         // zeroed by k_count each call, before gat1 accumulates
__device__ float g_sumsq[H1CH];

// ---------------- helpers ----------------
__device__ __forceinline__ float lrelu(float v) { return v > 0.f ? v : NEG_SLOPE * v; }
__device__ __forceinline__ float eluf(float v)  { return v > 0.f ? v : expm1f(v); }

__device__ __forceinline__ uint32_t pack_h2(float a, float b) {
    __half2 h = __floats2half2_rn(a, b);
    return *reinterpret_cast<uint32_t*>(&h);
}

__device__ __forceinline__ void mma_m16n8k16_f16(float* c, const uint32_t* a, const uint32_t* b) {
    asm volatile(
        "mma.sync.aligned.m16n8k16.row.col.f32.f16.f16.f32 "
        "{%0,%1,%2,%3}, {%4,%5,%6,%7}, {%8,%9}, {%0,%1,%2,%3};\n"
        : "+f"(c[0]), "+f"(c[1]), "+f"(c[2]), "+f"(c[3])
        : "r"(a[0]), "r"(a[1]), "r"(a[2]), "r"(a[3]), "r"(b[0]), "r"(b[1]));
}

// ---------------- weight prep: fp32 [K,N] -> fp16 [N,K] ----------------
__global__ void k_wprep(const float* __restrict__ W1l, const float* __restrict__ W1r,
                        const float* __restrict__ W2l, const float* __restrict__ W2r,
                        const float* __restrict__ Wc) {
    int i = blockIdx.x * blockDim.x + threadIdx.x;
    if (i < 256 * 128) {
        int nn = i >> 7, k = i & 127;
        float v = (nn < 128) ? W1l[k * 128 + nn] : W1r[k * 128 + nn - 128];
        g_w1h[i] = __float2half(v);
    }
    if (i < 64 * 128) {
        int nn = i >> 7, k = i & 127;
        float v = (nn < 32) ? W2l[k * 32 + nn] : W2r[k * 32 + nn - 32];
        g_w2h[i] = __float2half(v);
    }
    if (i < 64 * 160) {
        int nn = i / 160, k = i - nn * 160;
        g_wch[i] = __float2half(Wc[k * 64 + nn]);
    }
}

// ---------------- CSR build ----------------
__global__ void k_count(const int* __restrict__ ei, int e) {
    int i = blockIdx.x * blockDim.x + threadIdx.x;
    if (blockIdx.x == 0 && threadIdx.x < H1CH) {   // zero BN accumulators for this call
        g_sum[threadIdx.x] = 0.f;
        g_sumsq[threadIdx.x] = 0.f;
    }
    if (i < e) atomicAdd(&g_counts[ei[e + i]], 1);
}

// Single-block fused exclusive scan, COALESCED chunked walk:
// each 1024-wide chunk is block-scanned; running base carried in smem.
__global__ void k_scan_fused(int n, int e) {
    const int T = 1024;
    int t = threadIdx.x;
    int lane = t & 31, w = t >> 5;
    __shared__ int wsum[32];
    __shared__ int s_base;
    if (t == 0) s_base = 0;
    __syncthreads();

    for (int base = 0; base < n; base += T) {
        int i = base + t;
        int v = (i < n) ? g_counts[i] : 0;

        // warp inclusive scan
        int inc = v;
#pragma unroll
        for (int off = 1; off < 32; off <<= 1) {
            int u = __shfl_up_sync(0xffffffffu, inc, off);
            if (lane >= off) inc += u;
        }
        if (lane == 31) wsum[w] = inc;
        __syncthreads();

        if (w == 0) {   // scan warp totals in place
            int x = wsum[lane];
#pragma unroll
            for (int off = 1; off < 32; off <<= 1) {
                int u = __shfl_up_sync(0xffffffffu, x, off);
                if (lane >= off) x += u;
            }
            wsum[lane] = x;
        }
        __syncthreads();

        int wbase = (w == 0) ? 0 : wsum[w - 1];
        if (i < n) g_rowptr[i] = s_base + wbase + inc - v;
        __syncthreads();                     // all reads of s_base done
        if (t == 0) s_base += wsum[31];      // add chunk total
        __syncthreads();                     // also guards wsum reuse next iter
    }
    if (t == 0) g_rowptr[n] = e;
}

// atomicSub restores counts to zero for the next call (self-zeroing invariant)
__global__ void k_fill(const int* __restrict__ ei, int e) {
    int i = blockIdx.x * blockDim.x + threadIdx.x;
    if (i < e) {
        int d = ei[e + i];
        int s = ei[i];
        int c = atomicSub(&g_counts[d], 1);
        g_srcs[g_rowptr[d] + c - 1] = s;
    }
}

// ---------------- fp16 MMA GEMM (m16n8k16, smem holds fp16) ----------------
// MODE: 0 = plain fp32 A | 1 = elu(bn(g_h1)) K=128 | 2 = g_h2e K=32
// OUTM: 0 = fp32 C | 1 = outsel? g_xr1 : g_xl1h | 2 = split col 32: g_xl2h / g_xr2 | 3 = C +=
template <int BM, int BN, int WM_CNT, int WN_CNT, int MODE, int OUTM>
__device__ __forceinline__ void mma_gemm_body(
    const float* __restrict__ A, const __half* __restrict__ Bh,
    float* __restrict__ C, int M, int K, int ldk, int koff, int ldc,
    const float* __restrict__ bias,
    const float* __restrict__ gammap, const float* __restrict__ betap, int outsel)
{
    constexpr int BK = 32;
    constexpr int THREADS = WM_CNT * WN_CNT * 32;
    constexpr int WM = BM / WM_CNT;
    constexpr int WN = BN / WN_CNT;
    constexpr int MT = WM / 16;
    constexpr int NT = WN / 8;
    constexpr int LDA2 = BK / 2 + 2;   // 18 words, conflict-free
    constexpr int LDB2 = BK / 2 + 4;   // 20 words, conflict-free

    __shared__ uint32_t As2[BM][LDA2];
    __shared__ uint32_t Bs2[BN][LDB2];
    __shared__ float sc_s[H1CH], sh_s[H1CH];

    const int tid = threadIdx.x;
    const int wid = tid >> 5;
    const int lane = tid & 31;
    const int warpM = wid / WN_CNT;
    const int warpN = wid % WN_CNT;
    const int g = lane >> 2;
    const int tg = lane & 3;

    const int rowBase = blockIdx.x * BM;

    if (MODE == 1) {
        if (tid < H1CH) {
            float inv_n = 1.f / (float)M;
            float mu = g_sum[tid] * inv_n;
            float var = g_sumsq[tid] * inv_n - mu * mu;
            float rs = rsqrtf(var + BN_EPS);
            float s = rs * gammap[tid];
            sc_s[tid] = s;
            sh_s[tid] = betap[tid] - mu * s;
        }
        __syncthreads();
    }

    float acc[MT][NT][4];
#pragma unroll
    for (int mt = 0; mt < MT; mt++)
#pragma unroll
        for (int nt = 0; nt < NT; nt++)
#pragma unroll
            for (int i = 0; i < 4; i++) acc[mt][nt][i] = 0.f;

    for (int kt = 0; kt < K; kt += BK) {
        constexpr int A_F4 = BM * BK / 4;
#pragma unroll
        for (int it = 0; it < A_F4 / THREADS; it++) {
            int f = tid + it * THREADS;
            int r = f >> 3;
            int kq = (f & 7) << 2;
            int grow = rowBase + r;
            float4 v = make_float4(0.f, 0.f, 0.f, 0.f);
            if (grow < M) {
                if (MODE == 0) {
                    v = *reinterpret_cast<const float4*>(A + (size_t)grow * K + kt + kq);
                } else if (MODE == 1) {
                    v = *reinterpret_cast<const float4*>(&g_h1[(size_t)grow * 128 + kt + kq]);
                    int c = kt + kq;
                    v.x = eluf(fmaf(v.x, sc_s[c + 0], sh_s[c + 0]));
                    v.y = eluf(fmaf(v.y, sc_s[c + 1], sh_s[c + 1]));
                    v.z = eluf(fmaf(v.z, sc_s[c + 2], sh_s[c + 2]));
                    v.w = eluf(fmaf(v.w, sc_s[c + 3], sh_s[c + 3]));
                } else {
                    v = *reinterpret_cast<const float4*>(&g_h2e[(size_t)grow * 32 + kq]);
                }
            }
            uint2 hh;
            hh.x = pack_h2(v.x, v.y);
            hh.y = pack_h2(v.z, v.w);
            *reinterpret_cast<uint2*>(&As2[r][kq >> 1]) = hh;
        }
        constexpr int B_U4 = BN * (BK / 8);
#pragma unroll
        for (int it = 0; it < B_U4 / THREADS; it++) {
            int f = tid + it * THREADS;
            int r = f >> 2;
            int c = f & 3;
            uint4 v = *reinterpret_cast<const uint4*>(Bh + (size_t)r * ldk + koff + kt + c * 8);
            *reinterpret_cast<uint4*>(&Bs2[r][c << 2]) = v;
        }
        __syncthreads();

#pragma unroll
        for (int kk2 = 0; kk2 < BK / 2; kk2 += 8) {
            uint32_t af[MT][4];
#pragma unroll
            for (int mt = 0; mt < MT; mt++) {
                int m = warpM * WM + mt * 16;
                af[mt][0] = As2[m + g][kk2 + tg];
                af[mt][1] = As2[m + g + 8][kk2 + tg];
                af[mt][2] = As2[m + g][kk2 + tg + 4];
                af[mt][3] = As2[m + g + 8][kk2 + tg + 4];
            }
            uint32_t bf[NT][2];
#pragma unroll
            for (int nt = 0; nt < NT; nt++) {
                int nn = warpN * WN + nt * 8;
                bf[nt][0] = Bs2[nn + g][kk2 + tg];
                bf[nt][1] = Bs2[nn + g][kk2 + tg + 4];
            }
#pragma unroll
            for (int mt = 0; mt < MT; mt++)
#pragma unroll
                for (int nt = 0; nt < NT; nt++)
                    mma_m16n8k16_f16(acc[mt][nt], af[mt], bf[nt]);
        }
        __syncthreads();
    }

#pragma unroll
    for (int mt = 0; mt < MT; mt++) {
        int m0 = rowBase + warpM * WM + mt * 16 + g;
        int m1 = m0 + 8;
#pragma unroll
        for (int nt = 0; nt < NT; nt++) {
            int c0 = warpN * WN + nt * 8 + 2 * tg;
            float bx = 0.f, by = 0.f;
            if (bias) { bx = bias[c0]; by = bias[c0 + 1]; }
            float2 v0 = make_float2(acc[mt][nt][0] + bx, acc[mt][nt][1] + by);
            float2 v1 = make_float2(acc[mt][nt][2] + bx, acc[mt][nt][3] + by);
            if (OUTM == 0) {
                if (m0 < M) *reinterpret_cast<float2*>(&C[(size_t)m0 * ldc + c0]) = v0;
                if (m1 < M) *reinterpret_cast<float2*>(&C[(size_t)m1 * ldc + c0]) = v1;
            } else if (OUTM == 1) {
                if (outsel == 0) {
                    if (m0 < M) *reinterpret_cast<__half2*>(&g_xl1h[(size_t)m0 * 128 + c0]) = __floats2half2_rn(v0.x, v0.y);
                    if (m1 < M) *reinterpret_cast<__half2*>(&g_xl1h[(size_t)m1 * 128 + c0]) = __floats2half2_rn(v1.x, v1.y);
                } else {
                    if (m0 < M) *reinterpret_cast<float2*>(&g_xr1[(size_t)m0 * 128 + c0]) = v0;
                    if (m1 < M) *reinterpret_cast<float2*>(&g_xr1[(size_t)m1 * 128 + c0]) = v1;
                }
            } else if (OUTM == 2) {
                if (c0 < 32) {
                    if (m0 < M) *reinterpret_cast<__half2*>(&g_xl2h[(size_t)m0 * 32 + c0]) = __floats2half2_rn(v0.x, v0.y);
                    if (m1 < M) *reinterpret_cast<__half2*>(&g_xl2h[(size_t)m1 * 32 + c0]) = __floats2half2_rn(v1.x, v1.y);
                } else {
                    int cc = c0 - 32;
                    if (m0 < M) *reinterpret_cast<float2*>(&g_xr2[(size_t)m0 * 32 + cc]) = v0;
                    if (m1 < M) *reinterpret_cast<float2*>(&g_xr2[(size_t)m1 * 32 + cc]) = v1;
                }
            } else {   // accumulate
                if (m0 < M) {
                    float2 o = *reinterpret_cast<float2*>(&C[(size_t)m0 * ldc + c0]);
                    o.x += v0.x; o.y += v0.y;
                    *reinterpret_cast<float2*>(&C[(size_t)m0 * ldc + c0]) = o;
                }
                if (m1 < M) {
                    float2 o = *reinterpret_cast<float2*>(&C[(size_t)m1 * ldc + c0]);
                    o.x += v1.x; o.y += v1.y;
                    *reinterpret_cast<float2*>(&C[(size_t)m1 * ldc + c0]) = o;
                }
            }
        }
    }
}

__global__ void __launch_bounds__(256) k_gemm1(const float* __restrict__ x, int M) {
    const __half* B = g_w1h + (size_t)blockIdx.y * 128 * 128;
    mma_gemm_body<128, 128, 2, 4, 0, 1>(x, B, nullptr, M, 128, 128, 0, 0,
                                        nullptr, nullptr, nullptr, blockIdx.y);
}
__global__ void __launch_bounds__(256) k_gemm2(const float* __restrict__ gamma,
                                               const float* __restrict__ beta, int M) {
    mma_gemm_body<128, 64, 4, 2, 1, 2>(nullptr, g_w2h, nullptr, M, 128, 128, 0, 0,
                                       nullptr, gamma, beta, 0);
}
__global__ void __launch_bounds__(256) k_gemm3x(const float* __restrict__ x,
                                                const float* __restrict__ bc,
                                                float* __restrict__ out, int M) {
    mma_gemm_body<128, 64, 4, 2, 0, 0>(x, g_wch, out, M, 128, 160, 32, 64,
                                       bc, nullptr, nullptr, 0);
}
__global__ void __launch_bounds__(256) k_gemm3h(float* __restrict__ out, int M) {
    mma_gemm_body<128, 64, 4, 2, 2, 3>(nullptr, g_wch, out, M, 32, 160, 0, 64,
                                       nullptr, nullptr, nullptr, 0);
}

// ---------------- GAT layer 1: warp-per-node, fp16 gather, depth-2 prefetch ----------------
__device__ __forceinline__ float4 ldxl_h(int row, int lane) {
    uint2 raw = *reinterpret_cast<const uint2*>(&g_xl1h[(size_t)row * 128 + lane * 4]);
    __half2 h0 = *reinterpret_cast<__half2*>(&raw.x);
    __half2 h1 = *reinterpret_cast<__half2*>(&raw.y);
    float2 f0 = __half22float2(h0);
    float2 f1 = __half22float2(h1);
    return make_float4(f0.x, f0.y, f1.x, f1.y);
}

__global__ void k_gat1_agg(const float* __restrict__ att1, const float* __restrict__ b1, int n) {
    __shared__ float ssum[128], ssq[128];
    int tid = threadIdx.x;
    if (tid < 128) { ssum[tid] = 0.f; ssq[tid] = 0.f; }
    __syncthreads();

    int node = blockIdx.x * (blockDim.x >> 5) + (tid >> 5);
    int lane = tid & 31;

    if (node < n) {
        float4 xrv = *reinterpret_cast<const float4*>(&g_xr1[(size_t)node * 128 + lane * 4]);
        float4 attv = *reinterpret_cast<const float4*>(att1 + (lane >> 3) * HIDC + (lane & 7) * 4);

        float4 msg = ldxl_h(node, lane);   // self loop
        float p = lrelu(msg.x + xrv.x) * attv.x + lrelu(msg.y + xrv.y) * attv.y +
                  lrelu(msg.z + xrv.z) * attv.z + lrelu(msg.w + xrv.w) * attv.w;
        p += __shfl_xor_sync(0xffffffffu, p, 1);
        p += __shfl_xor_sync(0xffffffffu, p, 2);
        p += __shfl_xor_sync(0xffffffffu, p, 4);

        float m = p;
        float lsum = 1.f;
        float4 acc = msg;

        int beg = g_rowptr[node];
        int end = g_rowptr[node + 1];

        float4 pa = make_float4(0.f, 0.f, 0.f, 0.f);
        float4 pb = make_float4(0.f, 0.f, 0.f, 0.f);
        if (beg < end)     pa = ldxl_h(g_srcs[beg], lane);
        if (beg + 1 < end) pb = ldxl_h(g_srcs[beg + 1], lane);

        for (int i = beg; i < end; i++) {
            float4 cur = pa;
            pa = pb;
            if (i + 2 < end) pb = ldxl_h(g_srcs[i + 2], lane);   // depth-2 prefetch
            float q = lrelu(cur.x + xrv.x) * attv.x + lrelu(cur.y + xrv.y) * attv.y +
                      lrelu(cur.z + xrv.z) * attv.z + lrelu(cur.w + xrv.w) * attv.w;
            q += __shfl_xor_sync(0xffffffffu, q, 1);
            q += __shfl_xor_sync(0xffffffffu, q, 2);
            q += __shfl_xor_sync(0xffffffffu, q, 4);
            float mn = fmaxf(m, q);
            float sc = __expf(m - mn);
            float w = __expf(q - mn);
            lsum = lsum * sc + w;
            acc.x = acc.x * sc + w * cur.x;
            acc.y = acc.y * sc + w * cur.y;
            acc.z = acc.z * sc + w * cur.z;
            acc.w = acc.w * sc + w * cur.w;
            m = mn;
        }

        float inv = 1.f / lsum;
        float4 bvv = *reinterpret_cast<const float4*>(b1 + lane * 4);
        float4 o;
        o.x = acc.x * inv + bvv.x;
        o.y = acc.y * inv + bvv.y;
        o.z = acc.z * inv + bvv.z;
        o.w = acc.w * inv + bvv.w;
        reinterpret_cast<float4*>(g_h1)[node * 32 + lane] = o;

        int c = lane * 4;
        atomicAdd(&ssum[c + 0], o.x); atomicAdd(&ssq[c + 0], o.x * o.x);
        atomicAdd(&ssum[c + 1], o.y); atomicAdd(&ssq[c + 1], o.y * o.y);
        atomicAdd(&ssum[c + 2], o.z); atomicAdd(&ssq[c + 2], o.z * o.z);
        atomicAdd(&ssum[c + 3], o.w); atomicAdd(&ssq[c + 3], o.w * o.w);
    }

    __syncthreads();
    if (tid < 128) {
        atomicAdd(&g_sum[tid], ssum[tid]);
        atomicAdd(&g_sumsq[tid], ssq[tid]);
    }
}

// ---------------- GAT layer 2 (1 head, 32 ch), fp16 gather, depth-2 prefetch ----------------
__global__ void k_gat2_agg(const float* __restrict__ att2, const float* __restrict__ b2, int n) {
    int node = blockIdx.x * (blockDim.x >> 5) + (threadIdx.x >> 5);
    if (node >= n) return;
    int lane = threadIdx.x & 31;

    float xrc = g_xr2[(size_t)node * 32 + lane];
    float ac = att2[lane];

    float msg = __half2float(g_xl2h[(size_t)node * 32 + lane]);
    float p = lrelu(msg + xrc) * ac;
#pragma unroll
    for (int off = 16; off >= 1; off >>= 1) p += __shfl_xor_sync(0xffffffffu, p, off);

    float m = p, lsum = 1.f, acc = msg;

    int beg = g_rowptr[node];
    int end = g_rowptr[node + 1];

    float pa = 0.f, pb = 0.f;
    if (beg < end)     pa = __half2float(g_xl2h[(size_t)g_srcs[beg] * 32 + lane]);
    if (beg + 1 < end) pb = __half2float(g_xl2h[(size_t)g_srcs[beg + 1] * 32 + lane]);

    for (int i = beg; i < end; i++) {
        float cur = pa;
        pa = pb;
        if (i + 2 < end) pb = __half2float(g_xl2h[(size_t)g_srcs[i + 2] * 32 + lane]);
        float q = lrelu(cur + xrc) * ac;
#pragma unroll
        for (int off = 16; off >= 1; off >>= 1) q += __shfl_xor_sync(0xffffffffu, q, off);
        float mn = fmaxf(m, q);
        float sc = __expf(m - mn);
        float w = __expf(q - mn);
        lsum = lsum * sc + w;
        acc = acc * sc + w * cur;
        m = mn;
    }
    g_h2e[(size_t)node * 32 + lane] = eluf(acc / lsum + b2[lane]);
}

// ---------------- launch ----------------
extern "C" void kernel_launch(void* const* d_in, const int* in_sizes, int n_in,
                              void* d_out, int out_size) {
    const float* x     = (const float*)d_in[0];
    const int*   ei    = (const int*)d_in[1];
    const float* W1l   = (const float*)d_in[2];
    const float* W1r   = (const float*)d_in[3];
    const float* att1  = (const float*)d_in[4];
    const float* b1    = (const float*)d_in[5];
    const float* gamma = (const float*)d_in[6];
    const float* beta  = (const float*)d_in[7];
    const float* W2l   = (const float*)d_in[8];
    const float* W2r   = (const float*)d_in[9];
    const float* att2  = (const float*)d_in[10];
    const float* b2    = (const float*)d_in[11];
    const float* Wc    = (const float*)d_in[12];
    const float* bc    = (const float*)d_in[13];
    float* out = (float*)d_out;

    const int n = in_sizes[0] / IN_CH;   // 50000
    const int e = in_sizes[1] / 2;       // 800000

    // Side stream for CSR build + classifier x-part (host objects, created per
    // call and intentionally not destroyed; kernel_launch runs only a few times).
    cudaStream_t s2;
    cudaStreamCreateWithFlags(&s2, cudaStreamNonBlocking);
    cudaEvent_t evFork, evJoin1, evJoin2;
    cudaEventCreateWithFlags(&evFork, cudaEventDisableTiming);
    cudaEventCreateWithFlags(&evJoin1, cudaEventDisableTiming);
    cudaEventCreateWithFlags(&evJoin2, cudaEventDisableTiming);

    dim3 g2((n + 127) / 128, 1);

    // --- weight transpose/convert (feeds every GEMM incl. s2's gemm3x) ---
    k_wprep<<<(256 * 128 + 255) / 256, 256>>>(W1l, W1r, W2l, W2r, Wc);

    // fork: s2 branches off the (per-thread default) capture-origin stream
    cudaEventRecord(evFork, 0);
    cudaStreamWaitEvent(s2, evFork, 0);

    // --- s2: CSR build (also zeroes BN accumulators), then classifier x-part ---
    k_count<<<(e + 255) / 256, 256, 0, s2>>>(ei, e);
    k_scan_fused<<<1, 1024, 0, s2>>>(n, e);
    k_fill<<<(e + 255) / 256, 256, 0, s2>>>(ei, e);
    cudaEventRecord(evJoin1, s2);
    k_gemm3x<<<g2, 256, 0, s2>>>(x, bc, out, n);   // overlaps gat1/gemm2/gat2
    cudaEventRecord(evJoin2, s2);

    // --- main: conv1 projection concurrent with CSR ---
    dim3 g1((n + 127) / 128, 2);
    k_gemm1<<<g1, 256>>>(x, n);

    // join1: gat1 needs both gemm1 (main) and fill (s2)
    cudaStreamWaitEvent(0, evJoin1, 0);

    // --- conv1 edge softmax + aggregate (+b1), fused BN stats ---
    k_gat1_agg<<<(n + 7) / 8, 256>>>(att1, b1, n);

    // --- conv2 projection: elu(bn(h1)) @ [W2l|W2r] (BN folded in) ---
    k_gemm2<<<g2, 256>>>(gamma, beta, n);

    // --- conv2 edge softmax + aggregate, +b2, ELU ---
    k_gat2_agg<<<(n + 7) / 8, 256>>>(att2, b2, n);

    // join2: gemm3h accumulates into out, must follow gemm3x
    cudaStreamWaitEvent(0, evJoin2, 0);

    // --- classifier h-part: out += h2e @ Wc[0:32] ---
    k_gemm3h<<<g2, 256>>>(out, n);
}

// round 16
// speedup vs baseline: 1.2082x; 1.2082x over previous
#include <cuda_runtime.h>
#include <cuda_fp16.h>
#include <math.h>
#include <stdint.h>

// ---------------- problem constants ----------------
#define N_MAX   50000
#define E_MAX   800000
#define IN_CH   128
#define HIDC    32
#define H1CH    128
#define CATCH   160
#define OUTCH   64
#define NEG_SLOPE 0.2f
#define BN_EPS    1e-5f

// ---------------- device scratch ----------------
__device__ __half g_xl1h[N_MAX * 128];  // conv1 xl, fp16 (gathered per-edge)
__device__ float  g_xr1 [N_MAX * 128];  // conv1 xr, fp32
__device__ float  g_h1  [N_MAX * H1CH];
__device__ __half g_xl2h[N_MAX * 32];   // conv2 xl, fp16 (gathered per-edge)
__device__ float  g_xr2 [N_MAX * 32];   // conv2 xr, fp32
__device__ float  g_h2e [N_MAX * HIDC];

__device__ __half g_w1h[256 * 128];     // [n][k] fp16: n<128 -> W1l^T, else W1r^T
__device__ __half g_w2h[64 * 128];      // [n][k] fp16: n<32 -> W2l^T, else W2r^T
__device__ __half g_wch[64 * 160];      // [n][k] fp16: Wc^T

__device__ int   g_counts[N_MAX];       // zero at load; self-zeroing via atomicSub in k_fill
__device__ int   g_incl  [N_MAX];
__device__ int   g_rowptr[N_MAX + 1];
__device__ int   g_srcs  [E_MAX];
__device__ int   g_bsums [64];
__device__ int   g_boff  [64];

__device__ float g_sum  [H1CH];         // zeroed by k_count each call, before gat1 accumulates
__device__ float g_sumsq[H1CH];

// ---------------- helpers ----------------
__device__ __forceinline__ float lrelu(float v) { return v > 0.f ? v : NEG_SLOPE * v; }
__device__ __forceinline__ float eluf(float v)  { return v > 0.f ? v : expm1f(v); }

__device__ __forceinline__ uint32_t pack_h2(float a, float b) {
    __half2 h = __floats2half2_rn(a, b);
    return *reinterpret_cast<uint32_t*>(&h);
}

__device__ __forceinline__ void mma_m16n8k16_f16(float* c, const uint32_t* a, const uint32_t* b) {
    asm volatile(
        "mma.sync.aligned.m16n8k16.row.col.f32.f16.f16.f32 "
        "{%0,%1,%2,%3}, {%4,%5,%6,%7}, {%8,%9}, {%0,%1,%2,%3};\n"
        : "+f"(c[0]), "+f"(c[1]), "+f"(c[2]), "+f"(c[3])
        : "r"(a[0]), "r"(a[1]), "r"(a[2]), "r"(a[3]), "r"(b[0]), "r"(b[1]));
}

// ---------------- weight prep: fp32 [K,N] -> fp16 [N,K] ----------------
__global__ void k_wprep(const float* __restrict__ W1l, const float* __restrict__ W1r,
                        const float* __restrict__ W2l, const float* __restrict__ W2r,
                        const float* __restrict__ Wc) {
    int i = blockIdx.x * blockDim.x + threadIdx.x;
    if (i < 256 * 128) {
        int nn = i >> 7, k = i & 127;
        float v = (nn < 128) ? W1l[k * 128 + nn] : W1r[k * 128 + nn - 128];
        g_w1h[i] = __float2half(v);
    }
    if (i < 64 * 128) {
        int nn = i >> 7, k = i & 127;
        float v = (nn < 32) ? W2l[k * 32 + nn] : W2r[k * 32 + nn - 32];
        g_w2h[i] = __float2half(v);
    }
    if (i < 64 * 160) {
        int nn = i / 160, k = i - nn * 160;
        g_wch[i] = __float2half(Wc[k * 64 + nn]);
    }
}

// ---------------- CSR build ----------------
__global__ void k_count(const int* __restrict__ ei, int e) {
    int i = blockIdx.x * blockDim.x + threadIdx.x;
    if (blockIdx.x == 0 && threadIdx.x < H1CH) {   // zero BN accumulators for this call
        g_sum[threadIdx.x] = 0.f;
        g_sumsq[threadIdx.x] = 0.f;
    }
    if (i < e) atomicAdd(&g_counts[ei[e + i]], 1);
}

__global__ void k_scan1(int n) {
    __shared__ int sh[1024];
    int i = blockIdx.x * 1024 + threadIdx.x;
    int v = (i < n) ? g_counts[i] : 0;
    sh[threadIdx.x] = v;
    __syncthreads();
    for (int off = 1; off < 1024; off <<= 1) {
        int t = (threadIdx.x >= off) ? sh[threadIdx.x - off] : 0;
        __syncthreads();
        sh[threadIdx.x] += t;
        __syncthreads();
    }
    if (i < n) g_incl[i] = sh[threadIdx.x];
    if (threadIdx.x == 1023) g_bsums[blockIdx.x] = sh[1023];
}

__global__ void k_scan2(int nb) {
    int t = threadIdx.x;               // 64 threads, 2 warps
    int v = (t < nb) ? g_bsums[t] : 0;
    int lane = t & 31, w = t >> 5;
    int s = v;
#pragma unroll
    for (int off = 1; off < 32; off <<= 1) {
        int u = __shfl_up_sync(0xffffffffu, s, off);
        if (lane >= off) s += u;
    }
    __shared__ int wtot;
    if (w == 0 && lane == 31) wtot = s;
    __syncthreads();
    int base = (w == 1) ? wtot : 0;
    if (t < nb) g_boff[t] = base + s - v;
}

__global__ void k_scan3(int n, int e) {
    int i = blockIdx.x * 1024 + threadIdx.x;
    if (i < n) {
        int c = g_counts[i];
        int boff = g_boff[blockIdx.x];
        g_rowptr[i] = g_incl[i] - c + boff;
        if (i == n - 1) g_rowptr[n] = e;
    }
}

// atomicSub restores counts to zero for the next call (self-zeroing invariant)
__global__ void k_fill(const int* __restrict__ ei, int e) {
    int i = blockIdx.x * blockDim.x + threadIdx.x;
    if (i < e) {
        int d = ei[e + i];
        int s = ei[i];
        int c = atomicSub(&g_counts[d], 1);
        g_srcs[g_rowptr[d] + c - 1] = s;
    }
}

// ---------------- fp16 MMA GEMM (m16n8k16, smem holds fp16) ----------------
// MODE: 0 = plain fp32 A | 1 = elu(bn(g_h1)) K=128 | 2 = g_h2e K=32
// OUTM: 0 = fp32 C | 1 = outsel? g_xr1 : g_xl1h | 2 = split col 32: g_xl2h / g_xr2 | 3 = C +=
template <int BM, int BN, int WM_CNT, int WN_CNT, int MODE, int OUTM>
__device__ __forceinline__ void mma_gemm_body(
    const float* __restrict__ A, const __half* __restrict__ Bh,
    float* __restrict__ C, int M, int K, int ldk, int koff, int ldc,
    const float* __restrict__ bias,
    const float* __restrict__ gammap, const float* __restrict__ betap, int outsel)
{
    constexpr int BK = 32;
    constexpr int THREADS = WM_CNT * WN_CNT * 32;
    constexpr int WM = BM / WM_CNT;
    constexpr int WN = BN / WN_CNT;
    constexpr int MT = WM / 16;
    constexpr int NT = WN / 8;
    constexpr int LDA2 = BK / 2 + 2;   // 18 words, conflict-free
    constexpr int LDB2 = BK / 2 + 4;   // 20 words, conflict-free

    __shared__ uint32_t As2[BM][LDA2];
    __shared__ uint32_t Bs2[BN][LDB2];
    __shared__ float sc_s[H1CH], sh_s[H1CH];

    const int tid = threadIdx.x;
    const int wid = tid >> 5;
    const int lane = tid & 31;
    const int warpM = wid / WN_CNT;
    const int warpN = wid % WN_CNT;
    const int g = lane >> 2;
    const int tg = lane & 3;

    const int rowBase = blockIdx.x * BM;

    if (MODE == 1) {
        if (tid < H1CH) {
            float inv_n = 1.f / (float)M;
            float mu = g_sum[tid] * inv_n;
            float var = g_sumsq[tid] * inv_n - mu * mu;
            float rs = rsqrtf(var + BN_EPS);
            float s = rs * gammap[tid];
            sc_s[tid] = s;
            sh_s[tid] = betap[tid] - mu * s;
        }
        __syncthreads();
    }

    float acc[MT][NT][4];
#pragma unroll
    for (int mt = 0; mt < MT; mt++)
#pragma unroll
        for (int nt = 0; nt < NT; nt++)
#pragma unroll
            for (int i = 0; i < 4; i++) acc[mt][nt][i] = 0.f;

    for (int kt = 0; kt < K; kt += BK) {
        constexpr int A_F4 = BM * BK / 4;
#pragma unroll
        for (int it = 0; it < A_F4 / THREADS; it++) {
            int f = tid + it * THREADS;
            int r = f >> 3;
            int kq = (f & 7) << 2;
            int grow = rowBase + r;
            float4 v = make_float4(0.f, 0.f, 0.f, 0.f);
            if (grow < M) {
                if (MODE == 0) {
                    v = *reinterpret_cast<const float4*>(A + (size_t)grow * K + kt + kq);
                } else if (MODE == 1) {
                    v = *reinterpret_cast<const float4*>(&g_h1[(size_t)grow * 128 + kt + kq]);
                    int c = kt + kq;
                    v.x = eluf(fmaf(v.x, sc_s[c + 0], sh_s[c + 0]));
                    v.y = eluf(fmaf(v.y, sc_s[c + 1], sh_s[c + 1]));
                    v.z = eluf(fmaf(v.z, sc_s[c + 2], sh_s[c + 2]));
                    v.w = eluf(fmaf(v.w, sc_s[c + 3], sh_s[c + 3]));
                } else {
                    v = *reinterpret_cast<const float4*>(&g_h2e[(size_t)grow * 32 + kq]);
                }
            }
            uint2 hh;
            hh.x = pack_h2(v.x, v.y);
            hh.y = pack_h2(v.z, v.w);
            *reinterpret_cast<uint2*>(&As2[r][kq >> 1]) = hh;
        }
        constexpr int B_U4 = BN * (BK / 8);
#pragma unroll
        for (int it = 0; it < B_U4 / THREADS; it++) {
            int f = tid + it * THREADS;
            int r = f >> 2;
            int c = f & 3;
            uint4 v = *reinterpret_cast<const uint4*>(Bh + (size_t)r * ldk + koff + kt + c * 8);
            *reinterpret_cast<uint4*>(&Bs2[r][c << 2]) = v;
        }
        __syncthreads();

#pragma unroll
        for (int kk2 = 0; kk2 < BK / 2; kk2 += 8) {
            uint32_t af[MT][4];
#pragma unroll
            for (int mt = 0; mt < MT; mt++) {
                int m = warpM * WM + mt * 16;
                af[mt][0] = As2[m + g][kk2 + tg];
                af[mt][1] = As2[m + g + 8][kk2 + tg];
                af[mt][2] = As2[m + g][kk2 + tg + 4];
                af[mt][3] = As2[m + g + 8][kk2 + tg + 4];
            }
            uint32_t bf[NT][2];
#pragma unroll
            for (int nt = 0; nt < NT; nt++) {
                int nn = warpN * WN + nt * 8;
                bf[nt][0] = Bs2[nn + g][kk2 + tg];
                bf[nt][1] = Bs2[nn + g][kk2 + tg + 4];
            }
#pragma unroll
            for (int mt = 0; mt < MT; mt++)
#pragma unroll
                for (int nt = 0; nt < NT; nt++)
                    mma_m16n8k16_f16(acc[mt][nt], af[mt], bf[nt]);
        }
        __syncthreads();
    }

#pragma unroll
    for (int mt = 0; mt < MT; mt++) {
        int m0 = rowBase + warpM * WM + mt * 16 + g;
        int m1 = m0 + 8;
#pragma unroll
        for (int nt = 0; nt < NT; nt++) {
            int c0 = warpN * WN + nt * 8 + 2 * tg;
            float bx = 0.f, by = 0.f;
            if (bias) { bx = bias[c0]; by = bias[c0 + 1]; }
            float2 v0 = make_float2(acc[mt][nt][0] + bx, acc[mt][nt][1] + by);
            float2 v1 = make_float2(acc[mt][nt][2] + bx, acc[mt][nt][3] + by);
            if (OUTM == 0) {
                if (m0 < M) *reinterpret_cast<float2*>(&C[(size_t)m0 * ldc + c0]) = v0;
                if (m1 < M) *reinterpret_cast<float2*>(&C[(size_t)m1 * ldc + c0]) = v1;
            } else if (OUTM == 1) {
                if (outsel == 0) {
                    if (m0 < M) *reinterpret_cast<__half2*>(&g_xl1h[(size_t)m0 * 128 + c0]) = __floats2half2_rn(v0.x, v0.y);
                    if (m1 < M) *reinterpret_cast<__half2*>(&g_xl1h[(size_t)m1 * 128 + c0]) = __floats2half2_rn(v1.x, v1.y);
                } else {
                    if (m0 < M) *reinterpret_cast<float2*>(&g_xr1[(size_t)m0 * 128 + c0]) = v0;
                    if (m1 < M) *reinterpret_cast<float2*>(&g_xr1[(size_t)m1 * 128 + c0]) = v1;
                }
            } else if (OUTM == 2) {
                if (c0 < 32) {
                    if (m0 < M) *reinterpret_cast<__half2*>(&g_xl2h[(size_t)m0 * 32 + c0]) = __floats2half2_rn(v0.x, v0.y);
                    if (m1 < M) *reinterpret_cast<__half2*>(&g_xl2h[(size_t)m1 * 32 + c0]) = __floats2half2_rn(v1.x, v1.y);
                } else {
                    int cc = c0 - 32;
                    if (m0 < M) *reinterpret_cast<float2*>(&g_xr2[(size_t)m0 * 32 + cc]) = v0;
                    if (m1 < M) *reinterpret_cast<float2*>(&g_xr2[(size_t)m1 * 32 + cc]) = v1;
                }
            } else {   // OUTM == 3: accumulate into C
                if (m0 < M) {
                    float2 o = *reinterpret_cast<float2*>(&C[(size_t)m0 * ldc + c0]);
                    o.x += v0.x; o.y += v0.y;
                    *reinterpret_cast<float2*>(&C[(size_t)m0 * ldc + c0]) = o;
                }
                if (m1 < M) {
                    float2 o = *reinterpret_cast<float2*>(&C[(size_t)m1 * ldc + c0]);
                    o.x += v1.x; o.y += v1.y;
                    *reinterpret_cast<float2*>(&C[(size_t)m1 * ldc + c0]) = o;
                }
            }
        }
    }
}

__global__ void __launch_bounds__(256) k_gemm1(const float* __restrict__ x, int M) {
    const __half* B = g_w1h + (size_t)blockIdx.y * 128 * 128;
    mma_gemm_body<128, 128, 2, 4, 0, 1>(x, B, nullptr, M, 128, 128, 0, 0,
                                        nullptr, nullptr, nullptr, blockIdx.y);
}
__global__ void __launch_bounds__(256) k_gemm2(const float* __restrict__ gamma,
                                               const float* __restrict__ beta, int M) {
    mma_gemm_body<128, 64, 4, 2, 1, 2>(nullptr, g_w2h, nullptr, M, 128, 128, 0, 0,
                                       nullptr, gamma, beta, 0);
}
// classifier x-part: out = x @ Wc[32:160] + bc   (independent of whole GNN chain)
__global__ void __launch_bounds__(256) k_gemm3x(const float* __restrict__ x,
                                                const float* __restrict__ bc,
                                                float* __restrict__ out, int M) {
    mma_gemm_body<128, 64, 4, 2, 0, 0>(x, g_wch, out, M, 128, 160, 32, 64,
                                       bc, nullptr, nullptr, 0);
}
// classifier h-part: out += h2e @ Wc[0:32]   (K=32)
__global__ void __launch_bounds__(256) k_gemm3h(float* __restrict__ out, int M) {
    mma_gemm_body<128, 64, 4, 2, 2, 3>(nullptr, g_wch, out, M, 32, 160, 0, 64,
                                       nullptr, nullptr, nullptr, 0);
}

// ---------------- GAT layer 1: warp-per-node, fp16 gather, fused BN stats ----------------
__device__ __forceinline__ float4 ldxl_h(int row, int lane) {
    uint2 raw = *reinterpret_cast<const uint2*>(&g_xl1h[(size_t)row * 128 + lane * 4]);
    __half2 h0 = *reinterpret_cast<__half2*>(&raw.x);
    __half2 h1 = *reinterpret_cast<__half2*>(&raw.y);
    float2 f0 = __half22float2(h0);
    float2 f1 = __half22float2(h1);
    return make_float4(f0.x, f0.y, f1.x, f1.y);
}

__global__ void k_gat1_agg(const float* __restrict__ att1, const float* __restrict__ b1, int n) {
    __shared__ float ssum[128], ssq[128];
    int tid = threadIdx.x;
    if (tid < 128) { ssum[tid] = 0.f; ssq[tid] = 0.f; }
    __syncthreads();

    int node = blockIdx.x * (blockDim.x >> 5) + (tid >> 5);
    int lane = tid & 31;

    if (node < n) {
        float4 xrv = *reinterpret_cast<const float4*>(&g_xr1[(size_t)node * 128 + lane * 4]);
        float4 attv = *reinterpret_cast<const float4*>(att1 + (lane >> 3) * HIDC + (lane & 7) * 4);

        float4 msg = ldxl_h(node, lane);   // self loop
        float p = lrelu(msg.x + xrv.x) * attv.x + lrelu(msg.y + xrv.y) * attv.y +
                  lrelu(msg.z + xrv.z) * attv.z + lrelu(msg.w + xrv.w) * attv.w;
        p += __shfl_xor_sync(0xffffffffu, p, 1);
        p += __shfl_xor_sync(0xffffffffu, p, 2);
        p += __shfl_xor_sync(0xffffffffu, p, 4);

        float m = p;
        float lsum = 1.f;
        float4 acc = msg;

        int beg = g_rowptr[node];
        int end = g_rowptr[node + 1];

        float4 nmsg = make_float4(0.f, 0.f, 0.f, 0.f);
        if (beg < end) nmsg = ldxl_h(g_srcs[beg], lane);

        for (int i = beg; i < end; i++) {
            float4 cur = nmsg;
            if (i + 1 < end) nmsg = ldxl_h(g_srcs[i + 1], lane);
            float q = lrelu(cur.x + xrv.x) * attv.x + lrelu(cur.y + xrv.y) * attv.y +
                      lrelu(cur.z + xrv.z) * attv.z + lrelu(cur.w + xrv.w) * attv.w;
            q += __shfl_xor_sync(0xffffffffu, q, 1);
            q += __shfl_xor_sync(0xffffffffu, q, 2);
            q += __shfl_xor_sync(0xffffffffu, q, 4);
            float mn = fmaxf(m, q);
            float sc = __expf(m - mn);
            float w = __expf(q - mn);
            lsum = lsum * sc + w;
            acc.x = acc.x * sc + w * cur.x;
            acc.y = acc.y * sc + w * cur.y;
            acc.z = acc.z * sc + w * cur.z;
            acc.w = acc.w * sc + w * cur.w;
            m = mn;
        }

        float inv = 1.f / lsum;
        float4 bvv = *reinterpret_cast<const float4*>(b1 + lane * 4);
        float4 o;
        o.x = acc.x * inv + bvv.x;
        o.y = acc.y * inv + bvv.y;
        o.z = acc.z * inv + bvv.z;
        o.w = acc.w * inv + bvv.w;
        reinterpret_cast<float4*>(g_h1)[node * 32 + lane] = o;

        int c = lane * 4;
        atomicAdd(&ssum[c + 0], o.x); atomicAdd(&ssq[c + 0], o.x * o.x);
        atomicAdd(&ssum[c + 1], o.y); atomicAdd(&ssq[c + 1], o.y * o.y);
        atomicAdd(&ssum[c + 2], o.z); atomicAdd(&ssq[c + 2], o.z * o.z);
        atomicAdd(&ssum[c + 3], o.w); atomicAdd(&ssq[c + 3], o.w * o.w);
    }

    __syncthreads();
    if (tid < 128) {
        atomicAdd(&g_sum[tid], ssum[tid]);
        atomicAdd(&g_sumsq[tid], ssq[tid]);
    }
}

// ---------------- GAT layer 2 (1 head, 32 ch), fp16 gather ----------------
__global__ void k_gat2_agg(const float* __restrict__ att2, const float* __restrict__ b2, int n) {
    int node = blockIdx.x * (blockDim.x >> 5) + (threadIdx.x >> 5);
    if (node >= n) return;
    int lane = threadIdx.x & 31;

    float xrc = g_xr2[(size_t)node * 32 + lane];
    float ac = att2[lane];

    float msg = __half2float(g_xl2h[(size_t)node * 32 + lane]);
    float p = lrelu(msg + xrc) * ac;
#pragma unroll
    for (int off = 16; off >= 1; off >>= 1) p += __shfl_xor_sync(0xffffffffu, p, off);

    float m = p, lsum = 1.f, acc = msg;

    int beg = g_rowptr[node];
    int end = g_rowptr[node + 1];

    float nmsg = 0.f;
    if (beg < end) nmsg = __half2float(g_xl2h[(size_t)g_srcs[beg] * 32 + lane]);

    for (int i = beg; i < end; i++) {
        float cur = nmsg;
        if (i + 1 < end) nmsg = __half2float(g_xl2h[(size_t)g_srcs[i + 1] * 32 + lane]);
        float q = lrelu(cur + xrc) * ac;
#pragma unroll
        for (int off = 16; off >= 1; off >>= 1) q += __shfl_xor_sync(0xffffffffu, q, off);
        float mn = fmaxf(m, q);
        float sc = __expf(m - mn);
        float w = __expf(q - mn);
        lsum = lsum * sc + w;
        acc = acc * sc + w * cur;
        m = mn;
    }
    g_h2e[(size_t)node * 32 + lane] = eluf(acc / lsum + b2[lane]);
}

// ---------------- launch ----------------
extern "C" void kernel_launch(void* const* d_in, const int* in_sizes, int n_in,
                              void* d_out, int out_size) {
    const float* x     = (const float*)d_in[0];
    const int*   ei    = (const int*)d_in[1];
    const float* W1l   = (const float*)d_in[2];
    const float* W1r   = (const float*)d_in[3];
    const float* att1  = (const float*)d_in[4];
    const float* b1    = (const float*)d_in[5];
    const float* gamma = (const float*)d_in[6];
    const float* beta  = (const float*)d_in[7];
    const float* W2l   = (const float*)d_in[8];
    const float* W2r   = (const float*)d_in[9];
    const float* att2  = (const float*)d_in[10];
    const float* b2    = (const float*)d_in[11];
    const float* Wc    = (const float*)d_in[12];
    const float* bc    = (const float*)d_in[13];
    float* out = (float*)d_out;

    const int n = in_sizes[0] / IN_CH;   // 50000
    const int e = in_sizes[1] / 2;       // 800000
    const int nb = (n + 1023) / 1024;

    // Side stream for CSR build + classifier x-part (host objects, created per
    // call and intentionally not destroyed; kernel_launch runs only a few times).
    cudaStream_t s2;
    cudaStreamCreateWithFlags(&s2, cudaStreamNonBlocking);
    cudaEvent_t evFork, evJoin1, evJoin2;
    cudaEventCreateWithFlags(&evFork, cudaEventDisableTiming);
    cudaEventCreateWithFlags(&evJoin1, cudaEventDisableTiming);
    cudaEventCreateWithFlags(&evJoin2, cudaEventDisableTiming);

    dim3 g2((n + 127) / 128, 1);

    // --- weight transpose/convert (feeds every GEMM incl. s2's gemm3x) ---
    k_wprep<<<(256 * 128 + 255) / 256, 256>>>(W1l, W1r, W2l, W2r, Wc);

    // fork: s2 branches off the (per-thread default) capture-origin stream
    cudaEventRecord(evFork, 0);
    cudaStreamWaitEvent(s2, evFork, 0);

    // --- s2: CSR build (also zeroes BN accumulators), then classifier x-part ---
    k_count<<<(e + 255) / 256, 256, 0, s2>>>(ei, e);
    k_scan1<<<nb, 1024, 0, s2>>>(n);
    k_scan2<<<1, 64, 0, s2>>>(nb);
    k_scan3<<<nb, 1024, 0, s2>>>(n, e);
    k_fill<<<(e + 255) / 256, 256, 0, s2>>>(ei, e);
    cudaEventRecord(evJoin1, s2);
    k_gemm3x<<<g2, 256, 0, s2>>>(x, bc, out, n);   // overlaps gat1/gemm2/gat2
    cudaEventRecord(evJoin2, s2);

    // --- main: conv1 projection concurrent with CSR ---
    dim3 g1((n + 127) / 128, 2);
    k_gemm1<<<g1, 256>>>(x, n);

    // join1: gat1 needs both gemm1 (main) and fill (s2)
    cudaStreamWaitEvent(0, evJoin1, 0);

    // --- conv1 edge softmax + aggregate (+b1), fused BN stats ---
    k_gat1_agg<<<(n + 7) / 8, 256>>>(att1, b1, n);

    // --- conv2 projection: elu(bn(h1)) @ [W2l|W2r] (BN folded in) ---
    k_gemm2<<<g2, 256>>>(gamma, beta, n);

    // --- conv2 edge softmax + aggregate, +b2, ELU ---
    k_gat2_agg<<<(n + 7) / 8, 256>>>(att2, b2, n);

    // join2: gemm3h accumulates into out, must follow gemm3x
    cudaStreamWaitEvent(0, evJoin2, 0);

    // --- classifier h-part: out += h2e @ Wc[0:32] ---
    k_gemm3h<<<g2, 256>>>(out, n);
}

// round 17
// speedup vs baseline: 1.2175x; 1.0077x over previous
#include <cuda_runtime.h>
#include <cuda_fp16.h>
#include <math.h>
#include <stdint.h>

// ---------------- problem constants ----------------
#define N_MAX   50000
#define E_MAX   800000
#define IN_CH   128
#define HIDC    32
#define H1CH    128
#define CATCH   160
#define OUTCH   64
#define NEG_SLOPE 0.2f
#define BN_EPS    1e-5f

// ---------------- device scratch ----------------
__device__ __half g_xl1h[N_MAX * 128];  // conv1 xl, fp16 (gathered per-edge)
__device__ float  g_xr1 [N_MAX * 128];  // conv1 xr, fp32
__device__ float  g_h1  [N_MAX * H1CH];
__device__ __half g_xl2h[N_MAX * 32];   // conv2 xl, fp16 (gathered per-edge)
__device__ float  g_xr2 [N_MAX * 32];   // conv2 xr, fp32
__device__ float  g_h2e [N_MAX * HIDC];

__device__ __half g_w1h[256 * 128];     // [n][k] fp16: n<128 -> W1l^T, else W1r^T
__device__ __half g_w2h[64 * 128];      // [n][k] fp16: n<32 -> W2l^T, else W2r^T
__device__ __half g_wch[64 * 160];      // [n][k] fp16: Wc^T

__device__ int   g_counts[N_MAX];       // zero at load; set by k_count, re-zeroed by k_scan3
__device__ int   g_slot  [E_MAX];       // per-edge within-row slot (from k_count's atomicAdd)
__device__ int   g_incl  [N_MAX];
__device__ int   g_rowptr[N_MAX + 1];
__device__ int   g_srcs  [E_MAX];
__device__ int   g_bsums [64];

__device__ float g_sum  [H1CH];         // zeroed by k_count each call, before gat1 accumulates
__device__ float g_sumsq[H1CH];

// ---------------- helpers ----------------
__device__ __forceinline__ float lrelu(float v) { return v > 0.f ? v : NEG_SLOPE * v; }
__device__ __forceinline__ float eluf(float v)  { return v > 0.f ? v : expm1f(v); }

__device__ __forceinline__ uint32_t pack_h2(float a, float b) {
    __half2 h = __floats2half2_rn(a, b);
    return *reinterpret_cast<uint32_t*>(&h);
}

__device__ __forceinline__ void mma_m16n8k16_f16(float* c, const uint32_t* a, const uint32_t* b) {
    asm volatile(
        "mma.sync.aligned.m16n8k16.row.col.f32.f16.f16.f32 "
        "{%0,%1,%2,%3}, {%4,%5,%6,%7}, {%8,%9}, {%0,%1,%2,%3};\n"
        : "+f"(c[0]), "+f"(c[1]), "+f"(c[2]), "+f"(c[3])
        : "r"(a[0]), "r"(a[1]), "r"(a[2]), "r"(a[3]), "r"(b[0]), "r"(b[1]));
}

// ---------------- weight prep: fp32 [K,N] -> fp16 [N,K] ----------------
__global__ void k_wprep(const float* __restrict__ W1l, const float* __restrict__ W1r,
                        const float* __restrict__ W2l, const float* __restrict__ W2r,
                        const float* __restrict__ Wc) {
    int i = blockIdx.x * blockDim.x + threadIdx.x;
    if (i < 256 * 128) {
        int nn = i >> 7, k = i & 127;
        float v = (nn < 128) ? W1l[k * 128 + nn] : W1r[k * 128 + nn - 128];
        g_w1h[i] = __float2half(v);
    }
    if (i < 64 * 128) {
        int nn = i >> 7, k = i & 127;
        float v = (nn < 32) ? W2l[k * 32 + nn] : W2r[k * 32 + nn - 32];
        g_w2h[i] = __float2half(v);
    }
    if (i < 64 * 160) {
        int nn = i / 160, k = i - nn * 160;
        g_wch[i] = __float2half(Wc[k * 64 + nn]);
    }
}

// ---------------- CSR build ----------------
// count: bump per-destination counters, stash each edge's slot (atomicAdd return)
__global__ void k_count(const int* __restrict__ ei, int e) {
    int i = blockIdx.x * blockDim.x + threadIdx.x;
    if (blockIdx.x == 0 && threadIdx.x < H1CH) {   // zero BN accumulators for this call
        g_sum[threadIdx.x] = 0.f;
        g_sumsq[threadIdx.x] = 0.f;
    }
    if (i < e) {
        int d = ei[e + i];
        g_slot[i] = atomicAdd(&g_counts[d], 1);
    }
}

__global__ void k_scan1(int n) {
    __shared__ int sh[1024];
    int i = blockIdx.x * 1024 + threadIdx.x;
    int v = (i < n) ? g_counts[i] : 0;
    sh[threadIdx.x] = v;
    __syncthreads();
    for (int off = 1; off < 1024; off <<= 1) {
        int t = (threadIdx.x >= off) ? sh[threadIdx.x - off] : 0;
        __syncthreads();
        sh[threadIdx.x] += t;
        __syncthreads();
    }
    if (i < n) g_incl[i] = sh[threadIdx.x];
    if (threadIdx.x == 1023) g_bsums[blockIdx.x] = sh[1023];
}

// scan3 with folded block-offset computation: each block sums g_bsums[0..bid).
// Also re-zeroes g_counts (replay invariant: k_count sets, k_scan3 clears).
__global__ void k_scan3(int n, int e) {
    __shared__ int part[2];
    __shared__ int s_boff;
    int t = threadIdx.x;

    if (t < 64) {
        int v = (t < blockIdx.x) ? g_bsums[t] : 0;
#pragma unroll
        for (int off = 16; off >= 1; off >>= 1) v += __shfl_xor_sync(0xffffffffu, v, off);
        if ((t & 31) == 0) part[t >> 5] = v;
    }
    __syncthreads();
    if (t == 0) s_boff = part[0] + part[1];
    __syncthreads();

    int i = blockIdx.x * 1024 + t;
    if (i < n) {
        int c = g_counts[i];
        g_rowptr[i] = g_incl[i] - c + s_boff;
        g_counts[i] = 0;
        if (i == n - 1) g_rowptr[n] = e;
    }
}

// atomic-free fill: slot was stashed by k_count
__global__ void k_fill(const int* __restrict__ ei, int e) {
    int i = blockIdx.x * blockDim.x + threadIdx.x;
    if (i < e) {
        int d = ei[e + i];
        g_srcs[g_rowptr[d] + g_slot[i]] = ei[i];
    }
}

// ---------------- fp16 MMA GEMM (m16n8k16, smem holds fp16) ----------------
// MODE: 0 = plain fp32 A | 1 = elu(bn(g_h1)) K=128 | 2 = g_h2e K=32
// OUTM: 0 = fp32 C | 1 = outsel? g_xr1 : g_xl1h | 2 = split col 32: g_xl2h / g_xr2 | 3 = C +=
template <int BM, int BN, int WM_CNT, int WN_CNT, int MODE, int OUTM>
__device__ __forceinline__ void mma_gemm_body(
    const float* __restrict__ A, const __half* __restrict__ Bh,
    float* __restrict__ C, int M, int K, int ldk, int koff, int ldc,
    const float* __restrict__ bias,
    const float* __restrict__ gammap, const float* __restrict__ betap, int outsel)
{
    constexpr int BK = 32;
    constexpr int THREADS = WM_CNT * WN_CNT * 32;
    constexpr int WM = BM / WM_CNT;
    constexpr int WN = BN / WN_CNT;
    constexpr int MT = WM / 16;
    constexpr int NT = WN / 8;
    constexpr int LDA2 = BK / 2 + 2;   // 18 words, conflict-free
    constexpr int LDB2 = BK / 2 + 4;   // 20 words, conflict-free

    __shared__ uint32_t As2[BM][LDA2];
    __shared__ uint32_t Bs2[BN][LDB2];
    __shared__ float sc_s[H1CH], sh_s[H1CH];

    const int tid = threadIdx.x;
    const int wid = tid >> 5;
    const int lane = tid & 31;
    const int warpM = wid / WN_CNT;
    const int warpN = wid % WN_CNT;
    const int g = lane >> 2;
    const int tg = lane & 3;

    const int rowBase = blockIdx.x * BM;

    if (MODE == 1) {
        if (tid < H1CH) {
            float inv_n = 1.f / (float)M;
            float mu = g_sum[tid] * inv_n;
            float var = g_sumsq[tid] * inv_n - mu * mu;
            float rs = rsqrtf(var + BN_EPS);
            float s = rs * gammap[tid];
            sc_s[tid] = s;
            sh_s[tid] = betap[tid] - mu * s;
        }
        __syncthreads();
    }

    float acc[MT][NT][4];
#pragma unroll
    for (int mt = 0; mt < MT; mt++)
#pragma unroll
        for (int nt = 0; nt < NT; nt++)
#pragma unroll
            for (int i = 0; i < 4; i++) acc[mt][nt][i] = 0.f;

    for (int kt = 0; kt < K; kt += BK) {
        constexpr int A_F4 = BM * BK / 4;
#pragma unroll
        for (int it = 0; it < A_F4 / THREADS; it++) {
            int f = tid + it * THREADS;
            int r = f >> 3;
            int kq = (f & 7) << 2;
            int grow = rowBase + r;
            float4 v = make_float4(0.f, 0.f, 0.f, 0.f);
            if (grow < M) {
                if (MODE == 0) {
                    v = *reinterpret_cast<const float4*>(A + (size_t)grow * K + kt + kq);
                } else if (MODE == 1) {
                    v = *reinterpret_cast<const float4*>(&g_h1[(size_t)grow * 128 + kt + kq]);
                    int c = kt + kq;
                    v.x = eluf(fmaf(v.x, sc_s[c + 0], sh_s[c + 0]));
                    v.y = eluf(fmaf(v.y, sc_s[c + 1], sh_s[c + 1]));
                    v.z = eluf(fmaf(v.z, sc_s[c + 2], sh_s[c + 2]));
                    v.w = eluf(fmaf(v.w, sc_s[c + 3], sh_s[c + 3]));
                } else {
                    v = *reinterpret_cast<const float4*>(&g_h2e[(size_t)grow * 32 + kq]);
                }
            }
            uint2 hh;
            hh.x = pack_h2(v.x, v.y);
            hh.y = pack_h2(v.z, v.w);
            *reinterpret_cast<uint2*>(&As2[r][kq >> 1]) = hh;
        }
        constexpr int B_U4 = BN * (BK / 8);
#pragma unroll
        for (int it = 0; it < B_U4 / THREADS; it++) {
            int f = tid + it * THREADS;
            int r = f >> 2;
            int c = f & 3;
            uint4 v = *reinterpret_cast<const uint4*>(Bh + (size_t)r * ldk + koff + kt + c * 8);
            *reinterpret_cast<uint4*>(&Bs2[r][c << 2]) = v;
        }
        __syncthreads();

#pragma unroll
        for (int kk2 = 0; kk2 < BK / 2; kk2 += 8) {
            uint32_t af[MT][4];
#pragma unroll
            for (int mt = 0; mt < MT; mt++) {
                int m = warpM * WM + mt * 16;
                af[mt][0] = As2[m + g][kk2 + tg];
                af[mt][1] = As2[m + g + 8][kk2 + tg];
                af[mt][2] = As2[m + g][kk2 + tg + 4];
                af[mt][3] = As2[m + g + 8][kk2 + tg + 4];
            }
            uint32_t bf[NT][2];
#pragma unroll
            for (int nt = 0; nt < NT; nt++) {
                int nn = warpN * WN + nt * 8;
                bf[nt][0] = Bs2[nn + g][kk2 + tg];
                bf[nt][1] = Bs2[nn + g][kk2 + tg + 4];
            }
#pragma unroll
            for (int mt = 0; mt < MT; mt++)
#pragma unroll
                for (int nt = 0; nt < NT; nt++)
                    mma_m16n8k16_f16(acc[mt][nt], af[mt], bf[nt]);
        }
        __syncthreads();
    }

#pragma unroll
    for (int mt = 0; mt < MT; mt++) {
        int m0 = rowBase + warpM * WM + mt * 16 + g;
        int m1 = m0 + 8;
#pragma unroll
        for (int nt = 0; nt < NT; nt++) {
            int c0 = warpN * WN + nt * 8 + 2 * tg;
            float bx = 0.f, by = 0.f;
            if (bias) { bx = bias[c0]; by = bias[c0 + 1]; }
            float2 v0 = make_float2(acc[mt][nt][0] + bx, acc[mt][nt][1] + by);
            float2 v1 = make_float2(acc[mt][nt][2] + bx, acc[mt][nt][3] + by);
            if (OUTM == 0) {
                if (m0 < M) *reinterpret_cast<float2*>(&C[(size_t)m0 * ldc + c0]) = v0;
                if (m1 < M) *reinterpret_cast<float2*>(&C[(size_t)m1 * ldc + c0]) = v1;
            } else if (OUTM == 1) {
                if (outsel == 0) {
                    if (m0 < M) *reinterpret_cast<__half2*>(&g_xl1h[(size_t)m0 * 128 + c0]) = __floats2half2_rn(v0.x, v0.y);
                    if (m1 < M) *reinterpret_cast<__half2*>(&g_xl1h[(size_t)m1 * 128 + c0]) = __floats2half2_rn(v1.x, v1.y);
                } else {
                    if (m0 < M) *reinterpret_cast<float2*>(&g_xr1[(size_t)m0 * 128 + c0]) = v0;
                    if (m1 < M) *reinterpret_cast<float2*>(&g_xr1[(size_t)m1 * 128 + c0]) = v1;
                }
            } else if (OUTM == 2) {
                if (c0 < 32) {
                    if (m0 < M) *reinterpret_cast<__half2*>(&g_xl2h[(size_t)m0 * 32 + c0]) = __floats2half2_rn(v0.x, v0.y);
                    if (m1 < M) *reinterpret_cast<__half2*>(&g_xl2h[(size_t)m1 * 32 + c0]) = __floats2half2_rn(v1.x, v1.y);
                } else {
                    int cc = c0 - 32;
                    if (m0 < M) *reinterpret_cast<float2*>(&g_xr2[(size_t)m0 * 32 + cc]) = v0;
                    if (m1 < M) *reinterpret_cast<float2*>(&g_xr2[(size_t)m1 * 32 + cc]) = v1;
                }
            } else {   // OUTM == 3: accumulate into C
                if (m0 < M) {
                    float2 o = *reinterpret_cast<float2*>(&C[(size_t)m0 * ldc + c0]);
                    o.x += v0.x; o.y += v0.y;
                    *reinterpret_cast<float2*>(&C[(size_t)m0 * ldc + c0]) = o;
                }
                if (m1 < M) {
                    float2 o = *reinterpret_cast<float2*>(&C[(size_t)m1 * ldc + c0]);
                    o.x += v1.x; o.y += v1.y;
                    *reinterpret_cast<float2*>(&C[(size_t)m1 * ldc + c0]) = o;
                }
            }
        }
    }
}

__global__ void __launch_bounds__(256) k_gemm1(const float* __restrict__ x, int M) {
    const __half* B = g_w1h + (size_t)blockIdx.y * 128 * 128;
    mma_gemm_body<128, 128, 2, 4, 0, 1>(x, B, nullptr, M, 128, 128, 0, 0,
                                        nullptr, nullptr, nullptr, blockIdx.y);
}
__global__ void __launch_bounds__(256) k_gemm2(const float* __restrict__ gamma,
                                               const float* __restrict__ beta, int M) {
    mma_gemm_body<128, 64, 4, 2, 1, 2>(nullptr, g_w2h, nullptr, M, 128, 128, 0, 0,
                                       nullptr, gamma, beta, 0);
}
// classifier x-part: out = x @ Wc[32:160] + bc   (independent of whole GNN chain)
__global__ void __launch_bounds__(256) k_gemm3x(const float* __restrict__ x,
                                                const float* __restrict__ bc,
                                                float* __restrict__ out, int M) {
    mma_gemm_body<128, 64, 4, 2, 0, 0>(x, g_wch, out, M, 128, 160, 32, 64,
                                       bc, nullptr, nullptr, 0);
}
// classifier h-part: out += h2e @ Wc[0:32]   (K=32)
__global__ void __launch_bounds__(256) k_gemm3h(float* __restrict__ out, int M) {
    mma_gemm_body<128, 64, 4, 2, 2, 3>(nullptr, g_wch, out, M, 32, 160, 0, 64,
                                       nullptr, nullptr, nullptr, 0);
}

// ---------------- GAT layer 1: warp-per-node, fp16 gather, fused BN stats ----------------
__device__ __forceinline__ float4 ldxl_h(int row, int lane) {
    uint2 raw = *reinterpret_cast<const uint2*>(&g_xl1h[(size_t)row * 128 + lane * 4]);
    __half2 h0 = *reinterpret_cast<__half2*>(&raw.x);
    __half2 h1 = *reinterpret_cast<__half2*>(&raw.y);
    float2 f0 = __half22float2(h0);
    float2 f1 = __half22float2(h1);
    return make_float4(f0.x, f0.y, f1.x, f1.y);
}

__global__ void k_gat1_agg(const float* __restrict__ att1, const float* __restrict__ b1, int n) {
    __shared__ float ssum[128], ssq[128];
    int tid = threadIdx.x;
    if (tid < 128) { ssum[tid] = 0.f; ssq[tid] = 0.f; }
    __syncthreads();

    int node = blockIdx.x * (blockDim.x >> 5) + (tid >> 5);
    int lane = tid & 31;

    if (node < n) {
        float4 xrv = *reinterpret_cast<const float4*>(&g_xr1[(size_t)node * 128 + lane * 4]);
        float4 attv = *reinterpret_cast<const float4*>(att1 + (lane >> 3) * HIDC + (lane & 7) * 4);

        float4 msg = ldxl_h(node, lane);   // self loop
        float p = lrelu(msg.x + xrv.x) * attv.x + lrelu(msg.y + xrv.y) * attv.y +
                  lrelu(msg.z + xrv.z) * attv.z + lrelu(msg.w + xrv.w) * attv.w;
        p += __shfl_xor_sync(0xffffffffu, p, 1);
        p += __shfl_xor_sync(0xffffffffu, p, 2);
        p += __shfl_xor_sync(0xffffffffu, p, 4);

        float m = p;
        float lsum = 1.f;
        float4 acc = msg;

        int beg = g_rowptr[node];
        int end = g_rowptr[node + 1];

        float4 nmsg = make_float4(0.f, 0.f, 0.f, 0.f);
        if (beg < end) nmsg = ldxl_h(g_srcs[beg], lane);

        for (int i = beg; i < end; i++) {
            float4 cur = nmsg;
            if (i + 1 < end) nmsg = ldxl_h(g_srcs[i + 1], lane);
            float q = lrelu(cur.x + xrv.x) * attv.x + lrelu(cur.y + xrv.y) * attv.y +
                      lrelu(cur.z + xrv.z) * attv.z + lrelu(cur.w + xrv.w) * attv.w;
            q += __shfl_xor_sync(0xffffffffu, q, 1);
            q += __shfl_xor_sync(0xffffffffu, q, 2);
            q += __shfl_xor_sync(0xffffffffu, q, 4);
            float mn = fmaxf(m, q);
            float sc = __expf(m - mn);
            float w = __expf(q - mn);
            lsum = lsum * sc + w;
            acc.x = acc.x * sc + w * cur.x;
            acc.y = acc.y * sc + w * cur.y;
            acc.z = acc.z * sc + w * cur.z;
            acc.w = acc.w * sc + w * cur.w;
            m = mn;
        }

        float inv = 1.f / lsum;
        float4 bvv = *reinterpret_cast<const float4*>(b1 + lane * 4);
        float4 o;
        o.x = acc.x * inv + bvv.x;
        o.y = acc.y * inv + bvv.y;
        o.z = acc.z * inv + bvv.z;
        o.w = acc.w * inv + bvv.w;
        reinterpret_cast<float4*>(g_h1)[node * 32 + lane] = o;

        int c = lane * 4;
        atomicAdd(&ssum[c + 0], o.x); atomicAdd(&ssq[c + 0], o.x * o.x);
        atomicAdd(&ssum[c + 1], o.y); atomicAdd(&ssq[c + 1], o.y * o.y);
        atomicAdd(&ssum[c + 2], o.z); atomicAdd(&ssq[c + 2], o.z * o.z);
        atomicAdd(&ssum[c + 3], o.w); atomicAdd(&ssq[c + 3], o.w * o.w);
    }

    __syncthreads();
    if (tid < 128) {
        atomicAdd(&g_sum[tid], ssum[tid]);
        atomicAdd(&g_sumsq[tid], ssq[tid]);
    }
}

// ---------------- GAT layer 2 (1 head, 32 ch), fp16 gather ----------------
__global__ void k_gat2_agg(const float* __restrict__ att2, const float* __restrict__ b2, int n) {
    int node = blockIdx.x * (blockDim.x >> 5) + (threadIdx.x >> 5);
    if (node >= n) return;
    int lane = threadIdx.x & 31;

    float xrc = g_xr2[(size_t)node * 32 + lane];
    float ac = att2[lane];

    float msg = __half2float(g_xl2h[(size_t)node * 32 + lane]);
    float p = lrelu(msg + xrc) * ac;
#pragma unroll
    for (int off = 16; off >= 1; off >>= 1) p += __shfl_xor_sync(0xffffffffu, p, off);

    float m = p, lsum = 1.f, acc = msg;

    int beg = g_rowptr[node];
    int end = g_rowptr[node + 1];

    float nmsg = 0.f;
    if (beg < end) nmsg = __half2float(g_xl2h[(size_t)g_srcs[beg] * 32 + lane]);

    for (int i = beg; i < end; i++) {
        float cur = nmsg;
        if (i + 1 < end) nmsg = __half2float(g_xl2h[(size_t)g_srcs[i + 1] * 32 + lane]);
        float q = lrelu(cur + xrc) * ac;
#pragma unroll
        for (int off = 16; off >= 1; off >>= 1) q += __shfl_xor_sync(0xffffffffu, q, off);
        float mn = fmaxf(m, q);
        float sc = __expf(m - mn);
        float w = __expf(q - mn);
        lsum = lsum * sc + w;
        acc = acc * sc + w * cur;
        m = mn;
    }
    g_h2e[(size_t)node * 32 + lane] = eluf(acc / lsum + b2[lane]);
}

// ---------------- launch ----------------
extern "C" void kernel_launch(void* const* d_in, const int* in_sizes, int n_in,
                              void* d_out, int out_size) {
    const float* x     = (const float*)d_in[0];
    const int*   ei    = (const int*)d_in[1];
    const float* W1l   = (const float*)d_in[2];
    const float* W1r   = (const float*)d_in[3];
    const float* att1  = (const float*)d_in[4];
    const float* b1    = (const float*)d_in[5];
    const float* gamma = (const float*)d_in[6];
    const float* beta  = (const float*)d_in[7];
    const float* W2l   = (const float*)d_in[8];
    const float* W2r   = (const float*)d_in[9];
    const float* att2  = (const float*)d_in[10];
    const float* b2    = (const float*)d_in[11];
    const float* Wc    = (const float*)d_in[12];
    const float* bc    = (const float*)d_in[13];
    float* out = (float*)d_out;

    const int n = in_sizes[0] / IN_CH;   // 50000
    const int e = in_sizes[1] / 2;       // 800000
    const int nb = (n + 1023) / 1024;

    // Side stream for CSR build + classifier x-part (host objects, created per
    // call and intentionally not destroyed; kernel_launch runs only a few times).
    cudaStream_t s2;
    cudaStreamCreateWithFlags(&s2, cudaStreamNonBlocking);
    cudaEvent_t evFork, evW, evJoin1, evJoin2;
    cudaEventCreateWithFlags(&evFork, cudaEventDisableTiming);
    cudaEventCreateWithFlags(&evW, cudaEventDisableTiming);
    cudaEventCreateWithFlags(&evJoin1, cudaEventDisableTiming);
    cudaEventCreateWithFlags(&evJoin2, cudaEventDisableTiming);

    dim3 g2((n + 127) / 128, 1);

    // fork FIRST: s2 branches off the (per-thread default) capture-origin stream
    cudaEventRecord(evFork, 0);
    cudaStreamWaitEvent(s2, evFork, 0);

    // --- s2: CSR build (also zeroes BN accumulators) ---
    k_count<<<(e + 255) / 256, 256, 0, s2>>>(ei, e);
    k_scan1<<<nb, 1024, 0, s2>>>(n);
    k_scan3<<<nb, 1024, 0, s2>>>(n, e);   // folded block-offset sum + counts re-zero
    k_fill<<<(e + 255) / 256, 256, 0, s2>>>(ei, e);
    cudaEventRecord(evJoin1, s2);

    // --- main: weight prep (overlaps k_count), then conv1 projection ---
    k_wprep<<<(256 * 128 + 255) / 256, 256>>>(W1l, W1r, W2l, W2r, Wc);
    cudaEventRecord(evW, 0);
    dim3 g1((n + 127) / 128, 2);
    k_gemm1<<<g1, 256>>>(x, n);

    // s2: classifier x-part needs g_wch from wprep (main)
    cudaStreamWaitEvent(s2, evW, 0);
    k_gemm3x<<<g2, 256, 0, s2>>>(x, bc, out, n);   // overlaps gat1/gemm2/gat2
    cudaEventRecord(evJoin2, s2);

    // join1: gat1 needs both gemm1 (main) and fill (s2)
    cudaStreamWaitEvent(0, evJoin1, 0);

    // --- conv1 edge softmax + aggregate (+b1), fused BN stats ---
    k_gat1_agg<<<(n + 7) / 8, 256>>>(att1, b1, n);

    // --- conv2 projection: elu(bn(h1)) @ [W2l|W2r] (BN folded in) ---
    k_gemm2<<<g2, 256>>>(gamma, beta, n);

    // --- conv2 edge softmax + aggregate, +b2, ELU ---
    k_gat2_agg<<<(n + 7) / 8, 256>>>(att2, b2, n);

    // join2: gemm3h accumulates into out, must follow gemm3x
    cudaStreamWaitEvent(0, evJoin2, 0);

    // --- classifier h-part: out += h2e @ Wc[0:32] ---
    k_gemm3h<<<g2, 256>>>(out, n);
}